// round 9
// baseline (speedup 1.0000x reference)
#include <cuda_runtime.h>
#include <stdint.h>

#define BATCH 64
#define T 2048
#define HID 256
#define FAST 64
#define SLOW 256
#define VOCAB 64
#define TLOOP (T - 3)

typedef unsigned long long u64;

__device__ __forceinline__ int warp_incl_scan(int x, int lane) {
    #pragma unroll
    for (int off = 1; off < 32; off <<= 1) {
        int t = __shfl_up_sync(0xffffffffu, x, off);
        if (lane >= off) x += t;
    }
    return x;
}

// dynamic smem: s_emb[16384] floats (64KB) + s_seq[2048] ints (8KB)
#define DYN_SMEM (HID * VOCAB * 4 + T * 4)

__global__ void __launch_bounds__(512) fused_kernel(
    const int* __restrict__ seq,
    const float* __restrict__ emb,
    const float* __restrict__ Wg, const float* __restrict__ bg,
    const float* __restrict__ Wd, const float* __restrict__ bd,
    const float* __restrict__ Wq, const float* __restrict__ bq,
    const float* __restrict__ Wo, const float* __restrict__ bo,
    float* __restrict__ out)
{
    extern __shared__ float smem_dyn[];
    float* s_emb = smem_dyn;                        // [VOCAB*HID]
    int*   s_seq = (int*)(smem_dyn + VOCAB * HID);  // [T]

    __shared__ float s_wg[HID], s_wd[HID];
    __shared__ float s_dem[VOCAB];
    __shared__ int s_rankv[VOCAB];
    __shared__ int s_vid[VOCAB];
    __shared__ unsigned s_am[2];
    __shared__ int s_ccnt[64];
    __shared__ int s_cpre[64];
    __shared__ int s_ha[VOCAB];
    __shared__ int s_ht[VOCAB];
    __shared__ int s_h1[VOCAB];
    __shared__ int s_h2[VOCAB];
    __shared__ int s_c1[VOCAB];
    __shared__ int s_c2[VOCAB];
    __shared__ int s_mrank, s_m;
    __shared__ float s_qp[8][HID];      // q matvec partials
    __shared__ float s_q[HID];
    __shared__ float s_ctxp[512];
    __shared__ float s_ctx[HID];
    __shared__ float s_pv[VOCAB];
    __shared__ float s_w[VOCAB];
    __shared__ float s_r8[2];
    __shared__ float s_lp[16 * VOCAB];  // logits partials

    const int b = blockIdx.x;
    const int tid = threadIdx.x;
    const int wid = tid >> 5, lane = tid & 31;

    // ---- stage emb (64KB) + seq (8KB) into smem, full-MLP burst ----
    {
        const float4* pe = (const float4*)emb;      // emb is 16B-aligned
        float4* se4 = (float4*)s_emb;
        #pragma unroll
        for (int k = 0; k < 8; ++k)
            se4[tid + 512 * k] = pe[tid + 512 * k];
        ((int4*)s_seq)[tid] = ((const int4*)(seq + b * T))[tid];
        if (tid < HID) { s_wg[tid] = Wg[tid]; s_wd[tid] = Wd[tid]; }
        if (tid < 2) s_am[tid] = 0u;
        if (tid < VOCAB) { s_ha[tid] = 0; s_ht[tid] = 0; }
        if (tid == 0) s_mrank = -1;
    }
    __syncthreads();

    const int lv = s_seq[T - 1];

    if (tid < 256) {
        // ================= pipeline A =================
        const float bg0 = bg[0];
        const float bd0 = bd[0];
        #pragma unroll
        for (int rr = 0; rr < 8; ++rr) {
            const int row = wid * 8 + rr;
            const float* er = s_emb + row * HID;
            float ag = 0.f, ad = 0.f;
            #pragma unroll
            for (int k = 0; k < 8; ++k) {
                float e = er[lane + 32 * k];
                ag += e * s_wg[lane + 32 * k];
                ad += e * s_wd[lane + 32 * k];
            }
            #pragma unroll
            for (int off = 16; off > 0; off >>= 1) {
                ag += __shfl_xor_sync(0xffffffffu, ag, off);
                ad += __shfl_xor_sync(0xffffffffu, ad, off);
            }
            if (lane == 0) {
                s_dem[row] = ad + bd0;
                float ws = 1.f / (1.f + __expf(-(ag + bg0)));
                if (ws >= 0.4f) atomicOr(&s_am[row >> 5], 1u << (row & 31));
            }
        }
        asm volatile("bar.sync 1, 256;" ::: "memory");

        if (tid < VOCAB) {
            float dv = s_dem[tid];
            int rank = 0;
            #pragma unroll 8
            for (int u = 0; u < VOCAB; ++u) {
                float du = s_dem[u];
                if (du < dv || (du == dv && u < tid)) rank++;
            }
            s_rankv[tid] = rank;
            s_vid[rank] = tid;
        }
        asm volatile("bar.sync 1, 256;" ::: "memory");

        const u64 act = (u64)s_am[0] | ((u64)s_am[1] << 32);

        // pass 1: counts + FULL histogram; cache tokens/ballots in regs
        int toks[8];
        unsigned ball[8];
        bool av[8];
        #pragma unroll
        for (int i = 0; i < 8; ++i) {
            const int chunk = wid * 8 + i;
            const int t = chunk * 32 + lane;
            toks[i] = s_seq[t];
            av[i] = (t < TLOOP) && (((act >> toks[i]) & 1ull) != 0ull);
            ball[i] = __ballot_sync(0xffffffffu, av[i]);
            if (lane == 0) s_ccnt[chunk] = __popc(ball[i]);
            if (av[i]) atomicAdd(&s_ha[s_rankv[toks[i]]], 1);
        }
        asm volatile("bar.sync 1, 256;" ::: "memory");

        if (wid == 0) {
            int a0 = s_ccnt[2 * lane], a1 = s_ccnt[2 * lane + 1];
            int s = warp_incl_scan(a0 + a1, lane);
            int excl = s - a0 - a1;
            s_cpre[2 * lane] = excl;
            s_cpre[2 * lane + 1] = excl + a0;
            if (lane == 31) s_m = s;
        }
        asm volatile("bar.sync 1, 256;" ::: "memory");

        const int m = s_m;
        // slow_mask (needs only m)
        {
            const int ne_ = (m > FAST) ? (m - FAST) : 0;
            const int sc_ = (ne_ < SLOW) ? ne_ : SLOW;
            out[BATCH * VOCAB + b * SLOW + tid] = (tid < sc_) ? 1.f : 0.f;
        }
        // pass 2 (lite): only chunks overlapping [m-256, m]
        const unsigned lmask = (1u << lane) - 1u;
        const int wlo = m - 256;
        #pragma unroll
        for (int i = 0; i < 8; ++i) {
            const int chunk = wid * 8 + i;
            const int lo = s_cpre[chunk];
            const int cnt = __popc(ball[i]);
            if (lo + cnt >= wlo) {              // warp-uniform skip
                if (av[i]) {
                    const int yi = lo + __popc(ball[i] & lmask) + 1;
                    const int rk = s_rankv[toks[i]];
                    if (yi >= wlo && yi <= m - 1) atomicAdd(&s_ht[rk], 1);
                    if (yi == m) s_mrank = rk;
                }
            }
        }
    } else {
        // ================= pipeline B =================
        const int bw = wid - 8;       // 0..7
        // q matvec: warp bw owns rows h = bw*32..+31; float2 row loads
        const float2* Wq2 = (const float2*)Wq;      // Wq is 8B-aligned
        float2 a0 = make_float2(0.f, 0.f);
        float2 a1 = make_float2(0.f, 0.f);
        float2 a2 = make_float2(0.f, 0.f);
        float2 a3 = make_float2(0.f, 0.f);
        #pragma unroll 8
        for (int rr = 0; rr < 32; ++rr) {
            const int h = bw * 32 + rr;
            const float e = s_emb[lv * HID + h];
            const float2 v0 = Wq2[h * 128 + lane];
            const float2 v1 = Wq2[h * 128 + 32 + lane];
            const float2 v2 = Wq2[h * 128 + 64 + lane];
            const float2 v3 = Wq2[h * 128 + 96 + lane];
            a0.x += e * v0.x; a0.y += e * v0.y;
            a1.x += e * v1.x; a1.y += e * v1.y;
            a2.x += e * v2.x; a2.y += e * v2.y;
            a3.x += e * v3.x; a3.y += e * v3.y;
        }
        {
            float2* qp2 = (float2*)(s_qp[bw]);
            qp2[lane] = a0;
            qp2[32 + lane] = a1;
            qp2[64 + lane] = a2;
            qp2[96 + lane] = a3;
        }
        asm volatile("bar.sync 2, 256;" ::: "memory");

        // reduce partials: j = tid-256
        {
            const int j = tid - 256;
            float acc = bq[j];
            #pragma unroll
            for (int w = 0; w < 8; ++w) acc += s_qp[w][j];
            s_q[j] = acc;
        }
        asm volatile("bar.sync 2, 256;" ::: "memory");

        // p[v] = emb[v] . q  (8 warps x 8 vids, all LDS)
        #pragma unroll
        for (int rr = 0; rr < 8; ++rr) {
            const int v = bw * 8 + rr;
            const float* er = s_emb + v * HID;
            float acc = 0.f;
            #pragma unroll
            for (int k = 0; k < 8; ++k)
                acc += er[lane + 32 * k] * s_q[lane + 32 * k];
            #pragma unroll
            for (int off = 16; off > 0; off >>= 1)
                acc += __shfl_xor_sync(0xffffffffu, acc, off);
            if (lane == 0) s_pv[v] = acc;
        }
    }
    __syncthreads();

    const int m = s_m;
    const int ne = (m > FAST) ? (m - FAST) : 0;
    const int k1 = ne;
    const int k2 = (ne > SLOW) ? (ne - SLOW) : 0;
    const int mrank = s_mrank;

    if (tid < VOCAB) {
        int h1 = s_ha[tid] - (tid == mrank ? 1 : 0);
        s_h1[tid] = h1;
        s_h2[tid] = h1 - s_ht[tid];
    }
    __syncthreads();

    if (wid == 0) {
        int a1_ = s_h1[2 * lane], b1_ = s_h1[2 * lane + 1];
        int a2_ = s_h2[2 * lane], b2_ = s_h2[2 * lane + 1];
        int s1 = warp_incl_scan(a1_ + b1_, lane);
        int s2 = warp_incl_scan(a2_ + b2_, lane);
        int e1 = s1 - a1_ - b1_;
        int e2 = s2 - a2_ - b2_;
        s_c1[2 * lane] = e1;  s_c1[2 * lane + 1] = e1 + a1_;
        s_c2[2 * lane] = e2;  s_c2[2 * lane + 1] = e2 + a2_;
    }
    __syncthreads();

    int ct = 0;
    float p = 0.f;
    if (tid < VOCAB) {
        const int h1 = s_h1[tid], h2 = s_h2[tid];
        int e1 = k1 - s_c1[tid]; e1 = e1 < 0 ? 0 : e1; e1 = e1 > h1 ? h1 : e1;
        int e2 = k2 - s_c2[tid]; e2 = e2 < 0 ? 0 : e2; e2 = e2 > h2 ? h2 : e2;
        ct = (h1 - e1 + (tid == mrank ? 1 : 0)) + (e1 - e2);
        p = s_pv[s_vid[tid]];
    }

    if (wid < 2) {
        float v = (ct > 0) ? p : -3.402823466e38f;
        #pragma unroll
        for (int off = 16; off > 0; off >>= 1)
            v = fmaxf(v, __shfl_xor_sync(0xffffffffu, v, off));
        if (lane == 0) s_r8[wid] = v;
    }
    __syncthreads();
    const float mx = fmaxf(s_r8[0], s_r8[1]);
    __syncthreads();
    float e = 0.f;
    if (wid < 2) {
        e = (ct > 0) ? (float)ct * __expf(p - mx) : 0.f;
        float sm = e;
        #pragma unroll
        for (int off = 16; off > 0; off >>= 1)
            sm += __shfl_xor_sync(0xffffffffu, sm, off);
        if (lane == 0) s_r8[wid] = sm;
    }
    __syncthreads();
    const float tot = s_r8[0] + s_r8[1];
    const float inv = (tot > 0.f) ? (1.f / tot) : 0.f;
    if (tid < VOCAB) s_w[tid] = e * inv;
    __syncthreads();

    // ctx: 512 threads, h = tid&255, 32 ranks each (all LDS)
    {
        const int h = tid & 255;
        const int half = tid >> 8;
        float c = 0.f;
        #pragma unroll 8
        for (int rr = 0; rr < 32; ++rr) {
            const int r = half * 32 + rr;
            c += s_w[r] * s_emb[s_vid[r] * HID + h];
        }
        s_ctxp[tid] = c;
    }
    __syncthreads();
    if (tid < HID) s_ctx[tid] = s_ctxp[tid] + s_ctxp[tid + 256];
    __syncthreads();

    // logits: 16 warps x 16 Wo rows each, float2 row loads
    {
        const float2* Wo2 = (const float2*)Wo;      // Wo is 8B-aligned
        float2 acc = make_float2(0.f, 0.f);
        #pragma unroll
        for (int it = 0; it < 16; ++it) {
            const int row = wid * 16 + it;
            const float c = s_ctx[row];
            const float2 v = Wo2[row * 32 + lane];
            acc.x += c * v.x;
            acc.y += c * v.y;
        }
        ((float2*)(s_lp + wid * VOCAB))[lane] = acc;
    }
    __syncthreads();
    if (tid < VOCAB) {
        float acc = bo[tid];
        #pragma unroll
        for (int w = 0; w < 16; ++w) acc += s_lp[w * VOCAB + tid];
        out[b * VOCAB + tid] = acc;
    }
}

extern "C" void kernel_launch(void* const* d_in, const int* in_sizes, int n_in,
                              void* d_out, int out_size) {
    const int*   seq = (const int*)d_in[0];
    const float* emb = (const float*)d_in[1];
    const float* Wg  = (const float*)d_in[2];
    const float* bg  = (const float*)d_in[3];
    const float* Wd  = (const float*)d_in[4];
    const float* bd  = (const float*)d_in[5];
    const float* Wq  = (const float*)d_in[6];
    const float* bq  = (const float*)d_in[7];
    const float* Wo  = (const float*)d_in[8];
    const float* bo  = (const float*)d_in[9];
    float* out = (float*)d_out;

    static int attr_set = 0;
    if (!attr_set) {
        cudaFuncSetAttribute(fused_kernel,
                             cudaFuncAttributeMaxDynamicSharedMemorySize,
                             DYN_SMEM);
        attr_set = 1;
    }
    fused_kernel<<<BATCH, 512, DYN_SMEM>>>(seq, emb, Wg, bg, Wd, bd,
                                           Wq, bq, Wo, bo, out);
}